// round 14
// baseline (speedup 1.0000x reference)
#include <cuda_runtime.h>

// Shapes fixed by setup_inputs()
#define B  64
#define T  1024
#define DQ 1024
#define DV 512
#define A  128

#define NPROD    64
#define LIST_CAP 256
#define PM_CAP   4
#define NOISE_CAP 64
#define PF_ROWS  8
#define SPIN_MAX 131072

// Global scratch (no allocation allowed)
__device__ __align__(16) float    g_pq[B * A];
__device__            unsigned    g_rdy[B];      // zero-init; consumer resets
__device__ __align__(16) float    g_scr_align[B * T];
__device__ __align__(16) float    g_scr_ctx[B * DV];

// tanh via fast exp: tanh(x) = 1 - 2/(exp(2x)+1); stable at both tails
__device__ __forceinline__ float ftanh(float x) {
    return 1.0f - 2.0f / (1.0f + __expf(2.0f * x));
}

struct __align__(16) ProdS {
    float q[4][DQ];                // off 0 (float4-cast) — 16 KB
};
struct __align__(16) ConsS {
    float prev[T];                 // off 0     (float4-cast)
    float pfull[T];                // off 4096
    float al[T];                   // off 8192
    float pq[A];                   // off 12288 (float4-cast)
    float wv[A];                   // off 12800 (float4-cast)
    float pmr[PM_CAP][A];          // off 13312 (float4-cast; row stride 512B)
    float noise_v[NOISE_CAP];
    float pf[PF_ROWS][DV];         // 16 KB
    int   pf_t[PF_ROWS];
    int   t1[LIST_CAP];
    int   t2[LIST_CAP];
    float av2[LIST_CAP];
    unsigned char mk[T];           // (uchar4-cast; offset 4B multiple)
    unsigned words[32];
    int   base[33];
    float inv;
    int   nnz2, timed_out;
};
// 16B alignment guaranteed end-to-end (the R4/R5 union-misalignment bug fix).
union __align__(16) SmemU { ProdS p; ConsS c; };

__global__ void __launch_bounds__(512) sma_kernel(
    const float* __restrict__ query,           // [B,DQ]
    const float* __restrict__ memory,          // [B,T,DV]
    const float* __restrict__ pm,              // [B,T,A]
    const float* __restrict__ prev,            // [B,T]
    const unsigned char* __restrict__ mask,    // [B,T]
    const float* __restrict__ noise,           // [B,T]
    const float* __restrict__ Wq,              // [A,DQ]
    const float* __restrict__ v_dir,           // [A]
    const float* __restrict__ v_g,
    const float* __restrict__ v_bias,
    const float* __restrict__ score_bias,
    float* ctx,                                // [B,DV] or null -> scratch
    float* align_out)                          // [B,T]  or null -> scratch
{
    __shared__ SmemU u;
    const int tid  = threadIdx.x;
    const int lane = tid & 31;
    const int warp = tid >> 5;

    if (blockIdx.x < NPROD) {
        // ============ PRODUCER: pq[b0..b0+3, a_tile*32 .. +32) ============
        ProdS& S = u.p;
        const int a_tile = blockIdx.x & 3;
        const int b0     = (blockIdx.x >> 2) * 4;
        const int a0     = a_tile * 32 + warp;       // r=0 row for this warp
        const float4* w40 = reinterpret_cast<const float4*>(Wq + (size_t)a0 * DQ);

        // Issue BOTH DRAM waves back-to-back: query regs + r=0 Wq regs,
        // then commit query to smem. (Previously Wq serialized behind the BAR.)
        const float4* qg = reinterpret_cast<const float4*>(query + (size_t)b0 * DQ);
        float4 qa = qg[tid];
        float4 qb = qg[tid + 512];
        float4 wbuf[8];
#pragma unroll
        for (int k = 0; k < 8; ++k) wbuf[k] = w40[k * 32 + lane];
        float4* q4s = reinterpret_cast<float4*>(&S.q[0][0]);
        q4s[tid]       = qa;
        q4s[tid + 512] = qb;
        __syncthreads();

#pragma unroll
        for (int r = 0; r < 2; ++r) {
            const int a = a0 + r * 16;
            float acc0 = 0.f, acc1 = 0.f, acc2 = 0.f, acc3 = 0.f;
#pragma unroll
            for (int i = 0; i < 8; ++i) {
                float4 w;
                if (r == 0) w = wbuf[i];
                else        w = reinterpret_cast<const float4*>(Wq + (size_t)a * DQ)[i * 32 + lane];
                float4 q0 = reinterpret_cast<const float4*>(S.q[0])[i * 32 + lane];
                float4 q1 = reinterpret_cast<const float4*>(S.q[1])[i * 32 + lane];
                float4 q2 = reinterpret_cast<const float4*>(S.q[2])[i * 32 + lane];
                float4 q3 = reinterpret_cast<const float4*>(S.q[3])[i * 32 + lane];
                acc0 += w.x*q0.x + w.y*q0.y + w.z*q0.z + w.w*q0.w;
                acc1 += w.x*q1.x + w.y*q1.y + w.z*q1.z + w.w*q1.w;
                acc2 += w.x*q2.x + w.y*q2.y + w.z*q2.z + w.w*q2.w;
                acc3 += w.x*q3.x + w.y*q3.y + w.z*q3.z + w.w*q3.w;
            }
#pragma unroll
            for (int o = 16; o; o >>= 1) {
                acc0 += __shfl_xor_sync(0xFFFFFFFFu, acc0, o);
                acc1 += __shfl_xor_sync(0xFFFFFFFFu, acc1, o);
                acc2 += __shfl_xor_sync(0xFFFFFFFFu, acc2, o);
                acc3 += __shfl_xor_sync(0xFFFFFFFFu, acc3, o);
            }
            if (lane == 0) {
                g_pq[(size_t)(b0 + 0) * A + a] = acc0;
                g_pq[(size_t)(b0 + 1) * A + a] = acc1;
                g_pq[(size_t)(b0 + 2) * A + a] = acc2;
                g_pq[(size_t)(b0 + 3) * A + a] = acc3;
            }
        }
        __syncthreads();
        __threadfence();                        // release pq
        if (tid < 4) atomicAdd(&g_rdy[b0 + tid], 1u);
        return;
    }

    // ============ CONSUMER: one block per batch ============
    if (ctx == nullptr)       ctx       = g_scr_ctx;
    if (align_out == nullptr) align_out = g_scr_align;
    ConsS& S = u.c;
    const int b = blockIdx.x - NPROD;

    // --- C1: stage prev/mask, zero pfull, weight-norm scale ---
    if (tid < 256) {
        reinterpret_cast<float4*>(S.prev)[tid] =
            reinterpret_cast<const float4*>(prev + (size_t)b * T)[tid];
        reinterpret_cast<uchar4*>(S.mk)[tid] =
            reinterpret_cast<const uchar4*>(mask + (size_t)b * T)[tid];
    }
    S.pfull[tid]       = 0.f;
    S.pfull[tid + 512] = 0.f;
    const float sb = score_bias[0] + v_bias[0];
    if (warp == 15) {
        float v0 = v_dir[lane], v1 = v_dir[lane + 32];
        float v2 = v_dir[lane + 64], v3 = v_dir[lane + 96];
        float ss = v0*v0 + v1*v1 + v2*v2 + v3*v3;
#pragma unroll
        for (int o = 16; o; o >>= 1) ss += __shfl_xor_sync(0xFFFFFFFFu, ss, o);
        if (lane == 0) S.inv = v_g[0] * rsqrtf(ss);
    }
    __syncthreads();

    // --- C2: parallel bitmask compaction of nonzero-prev (ascending t) ---
    const float pa = S.prev[tid];
    const float pb = S.prev[tid + 512];
    {
        const unsigned wa = __ballot_sync(0xFFFFFFFFu, pa != 0.f);
        const unsigned wb = __ballot_sync(0xFFFFFFFFu, pb != 0.f);
        if (lane == 0) { S.words[warp] = wa; S.words[16 + warp] = wb; }
        __syncthreads();
        if (warp == 0) {
            const int c = __popc(S.words[lane]);
            int incl = c;
#pragma unroll
            for (int o = 1; o < 32; o <<= 1) {
                int n = __shfl_up_sync(0xFFFFFFFFu, incl, o);
                if (lane >= o) incl += n;
            }
            S.base[lane] = incl - c;
            if (lane == 31) S.base[32] = incl;
        }
        __syncthreads();
        if (pa != 0.f) {
            int pos = S.base[warp] + __popc(wa & ((1u << lane) - 1u));
            if (pos < LIST_CAP) S.t1[pos] = tid;
        }
        if (pb != 0.f) {
            int pos = S.base[16 + warp] + __popc(wb & ((1u << lane) - 1u));
            if (pos < LIST_CAP) S.t1[pos] = tid + 512;
        }
        __syncthreads();
    }
    const int  nnz     = S.base[32];
    const bool sparse1 = (nnz <= LIST_CAP);

    // --- C3: issue data-dependent prefetch LDGs into registers (overlap the wait) ---
    int   pft_loc[PF_ROWS];
    float pfr[PF_ROWS];
    float pmrr[A / 32];
    float nz_r = 0.f;
#pragma unroll
    for (int j = 0; j < PF_ROWS; ++j) {
        int i  = j >> 1;
        int tt = (sparse1 && i < nnz) ? S.t1[i] + (j & 1) : -1;
        if (tt >= T) tt = -1;
        pft_loc[j] = tt;
        pfr[j] = (tt >= 0) ? memory[((size_t)b * T + tt) * DV + tid] : 0.f;
    }
    if (sparse1 && warp < PM_CAP && warp < nnz) {
        const float* src = pm + ((size_t)b * T + S.t1[warp]) * A;
#pragma unroll
        for (int k = 0; k < A / 32; ++k) pmrr[k] = src[k * 32 + lane];
    }
    if (sparse1 && tid < NOISE_CAP && tid < nnz)
        nz_r = noise[(size_t)b * T + S.t1[tid]];

    // --- C4: bounded wait for producer pq; fallback computes locally (no hang) ---
    if (tid == 0) {
        volatile unsigned* flag = &g_rdy[b];   // producer updates via L2 atomics
        int spins = 0;
        while (*flag < 4u && spins < SPIN_MAX) { __nanosleep(32); ++spins; }
        S.timed_out = (spins >= SPIN_MAX);
        atomicExch(&g_rdy[b], 0u);             // reset for next replay
    }
    __syncthreads();
    if (!S.timed_out) {
        __threadfence();                       // acquire
        if (tid < A) S.pq[tid] = __ldcg(&g_pq[(size_t)b * A + tid]);
    } else {
        // Fallback: local pq (deterministic; producer writes identical values)
        const float4* qg = reinterpret_cast<const float4*>(query + (size_t)b * DQ);
        for (int a = warp; a < A; a += 16) {
            const float4* w4 = reinterpret_cast<const float4*>(Wq + (size_t)a * DQ);
            float acc = 0.f;
#pragma unroll
            for (int k = 0; k < 8; ++k) {
                float4 w = w4[k * 32 + lane];
                float4 q = qg[k * 32 + lane];
                acc += w.x*q.x + w.y*q.y + w.z*q.z + w.w*q.w;
            }
#pragma unroll
            for (int o = 16; o; o >>= 1) acc += __shfl_xor_sync(0xFFFFFFFFu, acc, o);
            if (lane == 0) S.pq[a] = acc;
        }
    }

    // --- C5: commit prefetches to smem; finish wv ---
#pragma unroll
    for (int j = 0; j < PF_ROWS; ++j)
        if (pft_loc[j] >= 0) S.pf[j][tid] = pfr[j];
    if (tid < PF_ROWS) S.pf_t[tid] = pft_loc[tid];
    if (sparse1 && warp < PM_CAP && warp < nnz) {
#pragma unroll
        for (int k = 0; k < A / 32; ++k) S.pmr[warp][k * 32 + lane] = pmrr[k];
    }
    if (sparse1 && tid < NOISE_CAP && tid < nnz) S.noise_v[tid] = nz_r;
    if (tid < A) S.wv[tid] = v_dir[tid] * S.inv;
    __syncthreads();

    // --- C6: score/sigmoid at needed positions ---
    const float4 qv  = reinterpret_cast<const float4*>(S.pq)[lane];
    const float4 wvv = reinterpret_cast<const float4*>(S.wv)[lane];
    if (sparse1) {
        for (int i = warp; i < nnz; i += 16) {
            const int t = S.t1[i];
            float4 x = (i < PM_CAP)
                ? reinterpret_cast<const float4*>(S.pmr[i])[lane]
                : reinterpret_cast<const float4*>(pm)[((size_t)b * T + t) * (A / 4) + lane];
            float s = ftanh(x.x + qv.x) * wvv.x
                    + ftanh(x.y + qv.y) * wvv.y
                    + ftanh(x.z + qv.z) * wvv.z
                    + ftanh(x.w + qv.w) * wvv.w;
#pragma unroll
            for (int o = 16; o; o >>= 1) s += __shfl_xor_sync(0xFFFFFFFFu, s, o);
            if (lane == 0) {
                float nz = (i < NOISE_CAP) ? S.noise_v[i] : noise[(size_t)b * T + t];
                float score = sb + s + 2.0f * nz;
                S.pfull[t] = 1.0f / (1.0f + __expf(-score));
            }
        }
    } else {
        for (int t = warp; t < T; t += 16) {
            if (S.prev[t] != 0.f) {
                float4 x = reinterpret_cast<const float4*>(pm)[((size_t)b * T + t) * (A / 4) + lane];
                float s = ftanh(x.x + qv.x) * wvv.x
                        + ftanh(x.y + qv.y) * wvv.y
                        + ftanh(x.z + qv.z) * wvv.z
                        + ftanh(x.w + qv.w) * wvv.w;
#pragma unroll
                for (int o = 16; o; o >>= 1) s += __shfl_xor_sync(0xFFFFFFFFu, s, o);
                if (lane == 0) {
                    float score = sb + s + 2.0f * noise[(size_t)b * T + t];
                    S.pfull[t] = 1.0f / (1.0f + __expf(-score));
                }
            }
        }
    }
    __syncthreads();

    // --- C7: alignment (gather form) + parallel compaction of nonzero alignment ---
    float al0, al1;
    {
        const int t = tid;
        float pv = S.prev[t];
        al0 = (pv != 0.f) ? pv * S.pfull[t] : 0.f;
        if (t > 0) {
            float pv0 = S.prev[t - 1];
            if (pv0 != 0.f) al0 += pv0 * (1.f - S.pfull[t - 1]);
        }
        if (S.mk[t]) al0 = 0.f;
        S.al[t] = al0;
        align_out[(size_t)b * T + t] = al0;
    }
    {
        const int t = tid + 512;
        float pv = S.prev[t];
        al1 = (pv != 0.f) ? pv * S.pfull[t] : 0.f;
        {
            float pv0 = S.prev[t - 1];
            if (pv0 != 0.f) al1 += pv0 * (1.f - S.pfull[t - 1]);
        }
        if (S.mk[t]) al1 = 0.f;
        S.al[t] = al1;
        align_out[(size_t)b * T + t] = al1;
    }
    {
        const unsigned wa = __ballot_sync(0xFFFFFFFFu, al0 != 0.f);
        const unsigned wb = __ballot_sync(0xFFFFFFFFu, al1 != 0.f);
        if (lane == 0) { S.words[warp] = wa; S.words[16 + warp] = wb; }
        __syncthreads();
        if (warp == 0) {
            const int c = __popc(S.words[lane]);
            int incl = c;
#pragma unroll
            for (int o = 1; o < 32; o <<= 1) {
                int n = __shfl_up_sync(0xFFFFFFFFu, incl, o);
                if (lane >= o) incl += n;
            }
            S.base[lane] = incl - c;
            if (lane == 31) S.base[32] = incl;
        }
        __syncthreads();
        if (al0 != 0.f) {
            int pos = S.base[warp] + __popc(wa & ((1u << lane) - 1u));
            if (pos < LIST_CAP) { S.t2[pos] = tid; S.av2[pos] = al0; }
        }
        if (al1 != 0.f) {
            int pos = S.base[16 + warp] + __popc(wb & ((1u << lane) - 1u));
            if (pos < LIST_CAP) { S.t2[pos] = tid + 512; S.av2[pos] = al1; }
        }
        if (tid == 0) S.nnz2 = S.base[32];
        __syncthreads();
    }

    // --- C8: context (512 threads == DV), exact-zero rows skipped ---
    const int n2 = S.nnz2;
    float acc = 0.f;
    if (n2 <= LIST_CAP) {
        for (int i = 0; i < n2; ++i) {
            const int t = S.t2[i];
            int j_hit = -1;
#pragma unroll
            for (int j = 0; j < PF_ROWS; ++j) if (S.pf_t[j] == t) j_hit = j;
            float val = (j_hit >= 0)
                ? S.pf[j_hit][tid]
                : memory[((size_t)b * T + t) * DV + tid];
            acc += S.av2[i] * val;
        }
    } else {
        for (int t = 0; t < T; ++t) {
            float a = S.al[t];
            if (a != 0.f) acc += a * memory[((size_t)b * T + t) * DV + tid];
        }
    }
    ctx[(size_t)b * DV + tid] = acc;
}

extern "C" void kernel_launch(void* const* d_in, const int* in_sizes, int n_in,
                              void* d_out, int out_size) {
    const float*         query  = (const float*)d_in[0];
    const float*         memory = (const float*)d_in[1];
    const float*         pm     = (const float*)d_in[2];
    const float*         prev   = (const float*)d_in[3];
    const unsigned char* mask   = (const unsigned char*)d_in[4];
    const float*         noise  = (const float*)d_in[5];
    const float*         Wq     = (const float*)d_in[6];
    const float*         v_dir  = (const float*)d_in[7];
    const float*         v_g    = (const float*)d_in[8];
    const float*         v_bias = (const float*)d_in[9];
    const float*         sbias  = (const float*)d_in[10];

    float* out = (float*)d_out;
    float* ctx;
    float* align_out;

    if (out_size >= B * DV + B * T) {          // concatenated (context, alignment)
        ctx = out;
        align_out = out + B * DV;
    } else if (out_size == B * T) {            // alignment only
        ctx = nullptr;                         // kernel falls back to __device__ scratch
        align_out = out;
    } else {                                   // context only
        ctx = out;
        align_out = nullptr;
    }

    sma_kernel<<<NPROD + B, 512>>>(query, memory, pm, prev, mask, noise,
                                   Wq, v_dir, v_g, v_bias, sbias, ctx, align_out);
}

// round 16
// speedup vs baseline: 1.0254x; 1.0254x over previous
#include <cuda_runtime.h>

// Shapes fixed by setup_inputs()
#define B  64
#define T  1024
#define DQ 1024
#define DV 512
#define A  128

#define NPROD    64
#define LIST_CAP 256
#define PM_CAP   4
#define NOISE_CAP 64
#define PF_ROWS  8
#define SPIN_MAX 131072

// Global scratch (no allocation allowed)
__device__ __align__(16) float    g_pq[B * A];
__device__            unsigned    g_rdy[B];      // zero-init; consumer resets
__device__ __align__(16) float    g_scr_align[B * T];
__device__ __align__(16) float    g_scr_ctx[B * DV];

// tanh via fast exp: tanh(x) = 1 - 2/(exp(2x)+1); stable at both tails
__device__ __forceinline__ float ftanh(float x) {
    return 1.0f - 2.0f / (1.0f + __expf(2.0f * x));
}

struct __align__(16) ProdS {
    float q[4][DQ];                // off 0 (float4-cast) — 16 KB
};
struct __align__(16) ConsS {
    float prev[T];                 // off 0     (float4-cast)
    float pfull[T];                // off 4096
    float al[T];                   // off 8192
    float pq[A];                   // off 12288 (float4-cast)
    float wv[A];                   // off 12800 (float4-cast)
    float pmr[PM_CAP][A];          // off 13312 (float4-cast; row stride 512B)
    float noise_v[NOISE_CAP];
    float pf[PF_ROWS][DV];         // 16 KB
    int   pf_t[PF_ROWS];
    int   t1[LIST_CAP];
    int   t2[LIST_CAP];
    float av2[LIST_CAP];
    unsigned char mk[T];           // (uchar4-cast; offset 4B multiple)
    unsigned words[32];
    int   base[33];
    float inv;
    int   nnz2, timed_out;
};
// 16B alignment guaranteed end-to-end (the R4/R5 union-misalignment bug fix).
union __align__(16) SmemU { ProdS p; ConsS c; };

__global__ void __launch_bounds__(512) sma_kernel(
    const float* __restrict__ query,           // [B,DQ]
    const float* __restrict__ memory,          // [B,T,DV]
    const float* __restrict__ pm,              // [B,T,A]
    const float* __restrict__ prev,            // [B,T]
    const unsigned char* __restrict__ mask,    // [B,T]
    const float* __restrict__ noise,           // [B,T]
    const float* __restrict__ Wq,              // [A,DQ]
    const float* __restrict__ v_dir,           // [A]
    const float* __restrict__ v_g,
    const float* __restrict__ v_bias,
    const float* __restrict__ score_bias,
    float* ctx,                                // [B,DV] or null -> scratch
    float* align_out)                          // [B,T]  or null -> scratch
{
    __shared__ SmemU u;
    const int tid  = threadIdx.x;
    const int lane = tid & 31;
    const int warp = tid >> 5;

    if (blockIdx.x < NPROD) {
        // ============ PRODUCER: pq[b0..b0+3, a_tile*32 .. +32) ============
        ProdS& S = u.p;
        const int a_tile = blockIdx.x & 3;
        const int b0     = (blockIdx.x >> 2) * 4;

        float4* q4s = reinterpret_cast<float4*>(&S.q[0][0]);
        const float4* qg = reinterpret_cast<const float4*>(query + (size_t)b0 * DQ);
        q4s[tid]       = qg[tid];
        q4s[tid + 512] = qg[tid + 512];
        __syncthreads();

#pragma unroll
        for (int r = 0; r < 2; ++r) {
            const int a = a_tile * 32 + warp + r * 16;
            const float4* w4 = reinterpret_cast<const float4*>(Wq + (size_t)a * DQ);
            float acc0 = 0.f, acc1 = 0.f, acc2 = 0.f, acc3 = 0.f;
#pragma unroll
            for (int i = 0; i < 8; ++i) {
                float4 w  = w4[i * 32 + lane];
                float4 q0 = reinterpret_cast<const float4*>(S.q[0])[i * 32 + lane];
                float4 q1 = reinterpret_cast<const float4*>(S.q[1])[i * 32 + lane];
                float4 q2 = reinterpret_cast<const float4*>(S.q[2])[i * 32 + lane];
                float4 q3 = reinterpret_cast<const float4*>(S.q[3])[i * 32 + lane];
                acc0 += w.x*q0.x + w.y*q0.y + w.z*q0.z + w.w*q0.w;
                acc1 += w.x*q1.x + w.y*q1.y + w.z*q1.z + w.w*q1.w;
                acc2 += w.x*q2.x + w.y*q2.y + w.z*q2.z + w.w*q2.w;
                acc3 += w.x*q3.x + w.y*q3.y + w.z*q3.z + w.w*q3.w;
            }
#pragma unroll
            for (int o = 16; o; o >>= 1) {
                acc0 += __shfl_xor_sync(0xFFFFFFFFu, acc0, o);
                acc1 += __shfl_xor_sync(0xFFFFFFFFu, acc1, o);
                acc2 += __shfl_xor_sync(0xFFFFFFFFu, acc2, o);
                acc3 += __shfl_xor_sync(0xFFFFFFFFu, acc3, o);
            }
            if (lane == 0) {
                g_pq[(size_t)(b0 + 0) * A + a] = acc0;
                g_pq[(size_t)(b0 + 1) * A + a] = acc1;
                g_pq[(size_t)(b0 + 2) * A + a] = acc2;
                g_pq[(size_t)(b0 + 3) * A + a] = acc3;
            }
        }
        __syncthreads();
        __threadfence();                        // release pq
        if (tid < 4) atomicAdd(&g_rdy[b0 + tid], 1u);
        return;
    }

    // ============ CONSUMER: one block per batch ============
    if (ctx == nullptr)       ctx       = g_scr_ctx;
    if (align_out == nullptr) align_out = g_scr_align;
    ConsS& S = u.c;
    const int b = blockIdx.x - NPROD;

    // --- C1: stage prev/mask, zero pfull, weight-norm scale ---
    if (tid < 256) {
        reinterpret_cast<float4*>(S.prev)[tid] =
            reinterpret_cast<const float4*>(prev + (size_t)b * T)[tid];
        reinterpret_cast<uchar4*>(S.mk)[tid] =
            reinterpret_cast<const uchar4*>(mask + (size_t)b * T)[tid];
    }
    S.pfull[tid]       = 0.f;
    S.pfull[tid + 512] = 0.f;
    const float sb = score_bias[0] + v_bias[0];
    if (warp == 15) {
        float v0 = v_dir[lane], v1 = v_dir[lane + 32];
        float v2 = v_dir[lane + 64], v3 = v_dir[lane + 96];
        float ss = v0*v0 + v1*v1 + v2*v2 + v3*v3;
#pragma unroll
        for (int o = 16; o; o >>= 1) ss += __shfl_xor_sync(0xFFFFFFFFu, ss, o);
        if (lane == 0) S.inv = v_g[0] * rsqrtf(ss);
    }
    __syncthreads();

    // --- C2: parallel bitmask compaction of nonzero-prev (ascending t) ---
    const float pa = S.prev[tid];
    const float pb = S.prev[tid + 512];
    {
        const unsigned wa = __ballot_sync(0xFFFFFFFFu, pa != 0.f);
        const unsigned wb = __ballot_sync(0xFFFFFFFFu, pb != 0.f);
        if (lane == 0) { S.words[warp] = wa; S.words[16 + warp] = wb; }
        __syncthreads();
        if (warp == 0) {
            const int c = __popc(S.words[lane]);
            int incl = c;
#pragma unroll
            for (int o = 1; o < 32; o <<= 1) {
                int n = __shfl_up_sync(0xFFFFFFFFu, incl, o);
                if (lane >= o) incl += n;
            }
            S.base[lane] = incl - c;
            if (lane == 31) S.base[32] = incl;
        }
        __syncthreads();
        if (pa != 0.f) {
            int pos = S.base[warp] + __popc(wa & ((1u << lane) - 1u));
            if (pos < LIST_CAP) S.t1[pos] = tid;
        }
        if (pb != 0.f) {
            int pos = S.base[16 + warp] + __popc(wb & ((1u << lane) - 1u));
            if (pos < LIST_CAP) S.t1[pos] = tid + 512;
        }
        __syncthreads();
    }
    const int  nnz     = S.base[32];
    const bool sparse1 = (nnz <= LIST_CAP);

    // --- C3: issue data-dependent prefetch LDGs into registers (overlap the wait) ---
    int   pft_loc[PF_ROWS];
    float pfr[PF_ROWS];
    float pmrr[A / 32];
    float nz_r = 0.f;
#pragma unroll
    for (int j = 0; j < PF_ROWS; ++j) {
        int i  = j >> 1;
        int tt = (sparse1 && i < nnz) ? S.t1[i] + (j & 1) : -1;
        if (tt >= T) tt = -1;
        pft_loc[j] = tt;
        pfr[j] = (tt >= 0) ? memory[((size_t)b * T + tt) * DV + tid] : 0.f;
    }
    if (sparse1 && warp < PM_CAP && warp < nnz) {
        const float* src = pm + ((size_t)b * T + S.t1[warp]) * A;
#pragma unroll
        for (int k = 0; k < A / 32; ++k) pmrr[k] = src[k * 32 + lane];
    }
    if (sparse1 && tid < NOISE_CAP && tid < nnz)
        nz_r = noise[(size_t)b * T + S.t1[tid]];

    // --- C4: bounded wait for producer pq; fallback computes locally (no hang) ---
    if (tid == 0) {
        int spins = 0;
        while (atomicAdd(&g_rdy[b], 0u) < 4u && spins < SPIN_MAX) { __nanosleep(64); ++spins; }
        S.timed_out = (spins >= SPIN_MAX);
        atomicExch(&g_rdy[b], 0u);             // reset for next replay
    }
    __syncthreads();
    if (!S.timed_out) {
        __threadfence();                       // acquire
        if (tid < A) S.pq[tid] = g_pq[(size_t)b * A + tid];
    } else {
        // Fallback: local pq (deterministic; producer writes identical values)
        const float4* qg = reinterpret_cast<const float4*>(query + (size_t)b * DQ);
        for (int a = warp; a < A; a += 16) {
            const float4* w4 = reinterpret_cast<const float4*>(Wq + (size_t)a * DQ);
            float acc = 0.f;
#pragma unroll
            for (int k = 0; k < 8; ++k) {
                float4 w = w4[k * 32 + lane];
                float4 q = qg[k * 32 + lane];
                acc += w.x*q.x + w.y*q.y + w.z*q.z + w.w*q.w;
            }
#pragma unroll
            for (int o = 16; o; o >>= 1) acc += __shfl_xor_sync(0xFFFFFFFFu, acc, o);
            if (lane == 0) S.pq[a] = acc;
        }
    }

    // --- C5: commit prefetches to smem; finish wv ---
#pragma unroll
    for (int j = 0; j < PF_ROWS; ++j)
        if (pft_loc[j] >= 0) S.pf[j][tid] = pfr[j];
    if (tid < PF_ROWS) S.pf_t[tid] = pft_loc[tid];
    if (sparse1 && warp < PM_CAP && warp < nnz) {
#pragma unroll
        for (int k = 0; k < A / 32; ++k) S.pmr[warp][k * 32 + lane] = pmrr[k];
    }
    if (sparse1 && tid < NOISE_CAP && tid < nnz) S.noise_v[tid] = nz_r;
    if (tid < A) S.wv[tid] = v_dir[tid] * S.inv;
    __syncthreads();

    // --- C6: score/sigmoid at needed positions ---
    const float4 qv  = reinterpret_cast<const float4*>(S.pq)[lane];
    const float4 wvv = reinterpret_cast<const float4*>(S.wv)[lane];
    if (sparse1) {
        for (int i = warp; i < nnz; i += 16) {
            const int t = S.t1[i];
            float4 x = (i < PM_CAP)
                ? reinterpret_cast<const float4*>(S.pmr[i])[lane]
                : reinterpret_cast<const float4*>(pm)[((size_t)b * T + t) * (A / 4) + lane];
            float s = ftanh(x.x + qv.x) * wvv.x
                    + ftanh(x.y + qv.y) * wvv.y
                    + ftanh(x.z + qv.z) * wvv.z
                    + ftanh(x.w + qv.w) * wvv.w;
#pragma unroll
            for (int o = 16; o; o >>= 1) s += __shfl_xor_sync(0xFFFFFFFFu, s, o);
            if (lane == 0) {
                float nz = (i < NOISE_CAP) ? S.noise_v[i] : noise[(size_t)b * T + t];
                float score = sb + s + 2.0f * nz;
                S.pfull[t] = 1.0f / (1.0f + __expf(-score));
            }
        }
    } else {
        for (int t = warp; t < T; t += 16) {
            if (S.prev[t] != 0.f) {
                float4 x = reinterpret_cast<const float4*>(pm)[((size_t)b * T + t) * (A / 4) + lane];
                float s = ftanh(x.x + qv.x) * wvv.x
                        + ftanh(x.y + qv.y) * wvv.y
                        + ftanh(x.z + qv.z) * wvv.z
                        + ftanh(x.w + qv.w) * wvv.w;
#pragma unroll
                for (int o = 16; o; o >>= 1) s += __shfl_xor_sync(0xFFFFFFFFu, s, o);
                if (lane == 0) {
                    float score = sb + s + 2.0f * noise[(size_t)b * T + t];
                    S.pfull[t] = 1.0f / (1.0f + __expf(-score));
                }
            }
        }
    }
    __syncthreads();

    // --- C7: alignment (gather form) + parallel compaction of nonzero alignment ---
    float al0, al1;
    {
        const int t = tid;
        float pv = S.prev[t];
        al0 = (pv != 0.f) ? pv * S.pfull[t] : 0.f;
        if (t > 0) {
            float pv0 = S.prev[t - 1];
            if (pv0 != 0.f) al0 += pv0 * (1.f - S.pfull[t - 1]);
        }
        if (S.mk[t]) al0 = 0.f;
        S.al[t] = al0;
        align_out[(size_t)b * T + t] = al0;
    }
    {
        const int t = tid + 512;
        float pv = S.prev[t];
        al1 = (pv != 0.f) ? pv * S.pfull[t] : 0.f;
        {
            float pv0 = S.prev[t - 1];
            if (pv0 != 0.f) al1 += pv0 * (1.f - S.pfull[t - 1]);
        }
        if (S.mk[t]) al1 = 0.f;
        S.al[t] = al1;
        align_out[(size_t)b * T + t] = al1;
    }
    {
        const unsigned wa = __ballot_sync(0xFFFFFFFFu, al0 != 0.f);
        const unsigned wb = __ballot_sync(0xFFFFFFFFu, al1 != 0.f);
        if (lane == 0) { S.words[warp] = wa; S.words[16 + warp] = wb; }
        __syncthreads();
        if (warp == 0) {
            const int c = __popc(S.words[lane]);
            int incl = c;
#pragma unroll
            for (int o = 1; o < 32; o <<= 1) {
                int n = __shfl_up_sync(0xFFFFFFFFu, incl, o);
                if (lane >= o) incl += n;
            }
            S.base[lane] = incl - c;
            if (lane == 31) S.base[32] = incl;
        }
        __syncthreads();
        if (al0 != 0.f) {
            int pos = S.base[warp] + __popc(wa & ((1u << lane) - 1u));
            if (pos < LIST_CAP) { S.t2[pos] = tid; S.av2[pos] = al0; }
        }
        if (al1 != 0.f) {
            int pos = S.base[16 + warp] + __popc(wb & ((1u << lane) - 1u));
            if (pos < LIST_CAP) { S.t2[pos] = tid + 512; S.av2[pos] = al1; }
        }
        if (tid == 0) S.nnz2 = S.base[32];
        __syncthreads();
    }

    // --- C8: context (512 threads == DV), exact-zero rows skipped ---
    const int n2 = S.nnz2;
    float acc = 0.f;
    if (n2 <= LIST_CAP) {
        for (int i = 0; i < n2; ++i) {
            const int t = S.t2[i];
            int j_hit = -1;
#pragma unroll
            for (int j = 0; j < PF_ROWS; ++j) if (S.pf_t[j] == t) j_hit = j;
            float val = (j_hit >= 0)
                ? S.pf[j_hit][tid]
                : memory[((size_t)b * T + t) * DV + tid];
            acc += S.av2[i] * val;
        }
    } else {
        for (int t = 0; t < T; ++t) {
            float a = S.al[t];
            if (a != 0.f) acc += a * memory[((size_t)b * T + t) * DV + tid];
        }
    }
    ctx[(size_t)b * DV + tid] = acc;
}

extern "C" void kernel_launch(void* const* d_in, const int* in_sizes, int n_in,
                              void* d_out, int out_size) {
    const float*         query  = (const float*)d_in[0];
    const float*         memory = (const float*)d_in[1];
    const float*         pm     = (const float*)d_in[2];
    const float*         prev   = (const float*)d_in[3];
    const unsigned char* mask   = (const unsigned char*)d_in[4];
    const float*         noise  = (const float*)d_in[5];
    const float*         Wq     = (const float*)d_in[6];
    const float*         v_dir  = (const float*)d_in[7];
    const float*         v_g    = (const float*)d_in[8];
    const float*         v_bias = (const float*)d_in[9];
    const float*         sbias  = (const float*)d_in[10];

    float* out = (float*)d_out;
    float* ctx;
    float* align_out;

    if (out_size >= B * DV + B * T) {          // concatenated (context, alignment)
        ctx = out;
        align_out = out + B * DV;
    } else if (out_size == B * T) {            // alignment only
        ctx = nullptr;                         // kernel falls back to __device__ scratch
        align_out = out;
    } else {                                   // context only
        ctx = out;
        align_out = nullptr;
    }

    sma_kernel<<<NPROD + B, 512>>>(query, memory, pm, prev, mask, noise,
                                   Wq, v_dir, v_g, v_bias, sbias, ctx, align_out);
}